// round 3
// baseline (speedup 1.0000x reference)
#include <cuda_runtime.h>

#define N_NODES 100000
#define N_EDGES 1600000

// Scratch (no cudaMalloc allowed)
__device__ float g_buf[N_NODES * 64];     // dinv-scaled transformed features (gather source)
__device__ float h_buf[N_NODES * 64];     // layer activation
__device__ float dinv_buf[N_NODES];       // rsqrt(deg+1)
__device__ int   deg_buf[N_NODES];        // in-degree (excl self-loop)
__device__ int   row_start[N_NODES + 1];  // CSR offsets (by dst)
__device__ int   cursor_buf[N_NODES];     // fill cursors
__device__ int   csr_src[N_EDGES];        // src grouped by dst
__device__ int   is64_flag;               // 1 if edge_index is int64, 0 if int32

// ---------------- dtype detection ----------------
// int64 little-endian with values < 2^31: every odd int32 word is 0.
__global__ void detect_dtype_kernel(const int* __restrict__ ei) {
    if (threadIdx.x == 0 && blockIdx.x == 0) {
        int any = 0;
        for (int k = 0; k < 64; k++) any |= ei[2 * k + 1];
        is64_flag = (any == 0) ? 1 : 0;
    }
}

__device__ __forceinline__ int load_src(const int* __restrict__ ei, int e, int is64) {
    return is64 ? ei[2 * e] : ei[e];
}
__device__ __forceinline__ int load_dst(const int* __restrict__ ei, int e, int is64) {
    return is64 ? ei[2 * (N_EDGES + e)] : ei[N_EDGES + e];
}

// ---------------- CSR build ----------------

__global__ void zero_counts_kernel() {
    int i = blockIdx.x * blockDim.x + threadIdx.x;
    if (i < N_NODES) { deg_buf[i] = 0; cursor_buf[i] = 0; }
}

__global__ void hist_kernel(const int* __restrict__ ei) {
    int e = blockIdx.x * blockDim.x + threadIdx.x;
    if (e >= N_EDGES) return;
    int d = load_dst(ei, e, is64_flag);
    atomicAdd(&deg_buf[d], 1);
}

__device__ __forceinline__ int block_inclusive_scan(int v, int tid) {
    __shared__ int warp_sums[32];
    int lane = tid & 31;
#pragma unroll
    for (int o = 1; o < 32; o <<= 1) {
        int n = __shfl_up_sync(0xffffffffu, v, o);
        if (lane >= o) v += n;
    }
    if (lane == 31) warp_sums[tid >> 5] = v;
    __syncthreads();
    if (tid < 32) {
        int w = warp_sums[tid];
#pragma unroll
        for (int o = 1; o < 32; o <<= 1) {
            int n = __shfl_up_sync(0xffffffffu, w, o);
            if (tid >= o) w += n;
        }
        warp_sums[tid] = w;
    }
    __syncthreads();
    if (tid >= 32) v += warp_sums[(tid >> 5) - 1];
    return v;
}

// single block, 1024 threads: exclusive scan of deg -> row_start, plus dinv
__global__ void scan_kernel() {
    int tid = threadIdx.x;
    __shared__ int carry_sh;
    if (tid == 0) carry_sh = 0;
    __syncthreads();
    for (int base = 0; base < N_NODES; base += 1024) {
        int i = base + tid;
        int v = (i < N_NODES) ? deg_buf[i] : 0;
        int inc = block_inclusive_scan(v, tid);
        int c = carry_sh;
        if (i < N_NODES) {
            row_start[i] = c + inc - v;
            dinv_buf[i] = rsqrtf((float)(v + 1));
        }
        __syncthreads();
        if (tid == 1023) carry_sh = c + inc;
        __syncthreads();
    }
    if (tid == 0) row_start[N_NODES] = carry_sh;
}

__global__ void fill_kernel(const int* __restrict__ ei) {
    int e = blockIdx.x * blockDim.x + threadIdx.x;
    if (e >= N_EDGES) return;
    int is64 = is64_flag;
    int s = load_src(ei, e, is64);
    int d = load_dst(ei, e, is64);
    int pos = atomicAdd(&cursor_buf[d], 1);
    csr_src[row_start[d] + pos] = s;
}

// ---------------- per-layer: GEMM + gather-aggregate ----------------

// g[i] = dinv[i] * (x[i] @ W). USE_H: read input from h_buf.
template <int IN, int OUT, bool USE_H>
__global__ void gemm_kernel(const float* __restrict__ xin, const float* __restrict__ W) {
    __shared__ float Ws[IN * OUT];
    for (int t = threadIdx.x; t < IN * OUT; t += blockDim.x) Ws[t] = W[t];
    __syncthreads();

    int i = blockIdx.x * blockDim.x + threadIdx.x;
    if (i >= N_NODES) return;
    const float* x = USE_H ? h_buf : xin;

    float o[OUT];
#pragma unroll
    for (int j = 0; j < OUT; j++) o[j] = 0.0f;
#pragma unroll
    for (int k = 0; k < IN; k++) {
        float xv = x[i * IN + k];
#pragma unroll
        for (int j = 0; j < OUT; j++) o[j] += xv * Ws[k * OUT + j];
    }
    float d = dinv_buf[i];
#pragma unroll
    for (int j = 0; j < OUT; j++) g_buf[i * OUT + j] = d * o[j];
}

// OUT=64: warp per node, 2 channels per lane. out = relu(dinv*sum + b)
__global__ void agg64_kernel(const float* __restrict__ b) {
    int w = (blockIdx.x * blockDim.x + threadIdx.x) >> 5;
    if (w >= N_NODES) return;
    int lane = threadIdx.x & 31;
    float a0 = g_buf[w * 64 + lane];          // self loop
    float a1 = g_buf[w * 64 + 32 + lane];
    int beg = row_start[w], end = row_start[w + 1];
    for (int k = beg; k < end; k++) {
        int s = csr_src[k];
        a0 += g_buf[s * 64 + lane];
        a1 += g_buf[s * 64 + 32 + lane];
    }
    float d = dinv_buf[w];
    h_buf[w * 64 + lane]      = fmaxf(fmaf(d, a0, b[lane]), 0.0f);
    h_buf[w * 64 + 32 + lane] = fmaxf(fmaf(d, a1, b[32 + lane]), 0.0f);
}

// OUT=32: warp per node, 1 channel per lane
__global__ void agg32_kernel(const float* __restrict__ b) {
    int w = (blockIdx.x * blockDim.x + threadIdx.x) >> 5;
    if (w >= N_NODES) return;
    int lane = threadIdx.x & 31;
    float a = g_buf[w * 32 + lane];
    int beg = row_start[w], end = row_start[w + 1];
    for (int k = beg; k < end; k++) {
        int s = csr_src[k];
        a += g_buf[s * 32 + lane];
    }
    h_buf[w * 32 + lane] = fmaxf(fmaf(dinv_buf[w], a, b[lane]), 0.0f);
}

// OUT=16: 16 threads per node (2 nodes per warp)
__global__ void agg16_kernel(const float* __restrict__ b) {
    int t = blockIdx.x * blockDim.x + threadIdx.x;
    int i = t >> 4;
    if (i >= N_NODES) return;
    int c = t & 15;
    float a = g_buf[i * 16 + c];
    int beg = row_start[i], end = row_start[i + 1];
    for (int k = beg; k < end; k++) {
        int s = csr_src[k];
        a += g_buf[s * 16 + c];
    }
    h_buf[i * 16 + c] = fmaxf(fmaf(dinv_buf[i], a, b[c]), 0.0f);
}

// OUT=2 final: thread per node, fused bias + log_softmax
__global__ void agg2_logsoftmax_kernel(const float* __restrict__ b, float* __restrict__ out) {
    int i = blockIdx.x * blockDim.x + threadIdx.x;
    if (i >= N_NODES) return;
    const float2* g2 = reinterpret_cast<const float2*>(g_buf);
    float2 a = g2[i];
    int beg = row_start[i], end = row_start[i + 1];
    for (int k = beg; k < end; k++) {
        float2 v = g2[csr_src[k]];
        a.x += v.x; a.y += v.y;
    }
    float d = dinv_buf[i];
    float v0 = fmaf(d, a.x, b[0]);
    float v1 = fmaf(d, a.y, b[1]);
    float m = fmaxf(v0, v1);
    float lse = m + logf(expf(v0 - m) + expf(v1 - m));
    out[i * 2 + 0] = v0 - lse;
    out[i * 2 + 1] = v1 - lse;
}

// ---------------- launch ----------------

extern "C" void kernel_launch(void* const* d_in, const int* in_sizes, int n_in,
                              void* d_out, int out_size) {
    const float* x  = (const float*)d_in[0];
    const int*   ei = (const int*)d_in[1];
    const float* W1 = (const float*)d_in[2];
    const float* b1 = (const float*)d_in[3];
    const float* W2 = (const float*)d_in[4];
    const float* b2 = (const float*)d_in[5];
    const float* W3 = (const float*)d_in[6];
    const float* b3 = (const float*)d_in[7];
    const float* W4 = (const float*)d_in[8];
    const float* b4 = (const float*)d_in[9];
    float* out = (float*)d_out;

    const int T = 256;
    const int nodeB = (N_NODES + T - 1) / T;
    const int edgeB = (N_EDGES + T - 1) / T;

    // dtype detection + CSR build (group by dst)
    detect_dtype_kernel<<<1, 32>>>(ei);
    zero_counts_kernel<<<nodeB, T>>>();
    hist_kernel<<<edgeB, T>>>(ei);
    scan_kernel<<<1, 1024>>>();
    fill_kernel<<<edgeB, T>>>(ei);

    // Layer 1: 18 -> 64
    gemm_kernel<18, 64, false><<<nodeB, T>>>(x, W1);
    agg64_kernel<<<(N_NODES * 32 + T - 1) / T, T>>>(b1);

    // Layer 2: 64 -> 32
    gemm_kernel<64, 32, true><<<nodeB, T>>>(nullptr, W2);
    agg32_kernel<<<(N_NODES * 32 + T - 1) / T, T>>>(b2);

    // Layer 3: 32 -> 16
    gemm_kernel<32, 16, true><<<nodeB, T>>>(nullptr, W3);
    agg16_kernel<<<(N_NODES * 16 + T - 1) / T, T>>>(b3);

    // Layer 4: 16 -> 2, log_softmax
    gemm_kernel<16, 2, true><<<nodeB, T>>>(nullptr, W4);
    agg2_logsoftmax_kernel<<<nodeB, T>>>(b4, out);
}

// round 4
// speedup vs baseline: 1.3327x; 1.3327x over previous
#include <cuda_runtime.h>

#define N_NODES 100000
#define N_EDGES 1600000

// Scratch (no cudaMalloc allowed). Ping-pong buffers A and B.
__device__ float A_buf[N_NODES * 64];
__device__ float B_buf[N_NODES * 64];
__device__ float dinv_buf[N_NODES];       // rsqrt(deg+1)
__device__ int   deg_buf[N_NODES];        // in-degree (excl self-loop)
__device__ int   row_start[N_NODES];      // CSR segment start (by dst, arbitrary order)
__device__ int   cursor_buf[N_NODES];     // fill cursors
__device__ int   csr_src[N_EDGES];        // src grouped by dst
__device__ int   is64_flag;               // 1 if edge_index is int64, 0 if int32
__device__ int   total_counter;           // segment allocator

// ---------------- dtype detection ----------------
// int64 little-endian with values < 2^31: every odd int32 word is 0.
__global__ void detect_dtype_kernel(const int* __restrict__ ei) {
    if (threadIdx.x == 0 && blockIdx.x == 0) {
        int any = 0;
        for (int k = 0; k < 64; k++) any |= ei[2 * k + 1];
        is64_flag = (any == 0) ? 1 : 0;
        total_counter = 0;
    }
}

__device__ __forceinline__ int load_src(const int* __restrict__ ei, int e, int is64) {
    return is64 ? ei[2 * e] : ei[e];
}
__device__ __forceinline__ int load_dst(const int* __restrict__ ei, int e, int is64) {
    return is64 ? ei[2 * (N_EDGES + e)] : ei[N_EDGES + e];
}

// ---------------- CSR build ----------------

__global__ void zero_counts_kernel() {
    int i = blockIdx.x * blockDim.x + threadIdx.x;
    if (i < N_NODES) { deg_buf[i] = 0; cursor_buf[i] = 0; }
}

__global__ void hist_kernel(const int* __restrict__ ei) {
    int e = blockIdx.x * blockDim.x + threadIdx.x;
    if (e >= N_EDGES) return;
    int d = load_dst(ei, e, is64_flag);
    atomicAdd(&deg_buf[d], 1);
}

__device__ __forceinline__ int block_inclusive_scan(int v, int tid) {
    __shared__ int warp_sums[32];
    int lane = tid & 31;
#pragma unroll
    for (int o = 1; o < 32; o <<= 1) {
        int n = __shfl_up_sync(0xffffffffu, v, o);
        if (lane >= o) v += n;
    }
    if (lane == 31) warp_sums[tid >> 5] = v;
    __syncthreads();
    if (tid < 32) {
        int w = warp_sums[tid];
#pragma unroll
        for (int o = 1; o < 32; o <<= 1) {
            int n = __shfl_up_sync(0xffffffffu, w, o);
            if (tid >= o) w += n;
        }
        warp_sums[tid] = w;
    }
    __syncthreads();
    return (tid >= 32) ? v + warp_sums[(tid >> 5) - 1] : v;
}

// Segment allocation: block-local exclusive scan + one atomic per block for the base.
// Segment ORDER across blocks is arbitrary — each node only needs its own contiguous range.
__global__ void alloc_kernel() {
    int tid = threadIdx.x;
    int i = blockIdx.x * 1024 + tid;
    int v = (i < N_NODES) ? deg_buf[i] : 0;
    int inc = block_inclusive_scan(v, tid);
    __shared__ int base_sh;
    if (tid == 1023) base_sh = atomicAdd(&total_counter, inc);
    __syncthreads();
    if (i < N_NODES) {
        row_start[i] = base_sh + inc - v;
        dinv_buf[i] = rsqrtf((float)(v + 1));
    }
}

__global__ void fill_kernel(const int* __restrict__ ei) {
    int e = blockIdx.x * blockDim.x + threadIdx.x;
    if (e >= N_EDGES) return;
    int is64 = is64_flag;
    int s = load_src(ei, e, is64);
    int d = load_dst(ei, e, is64);
    int pos = atomicAdd(&cursor_buf[d], 1);
    csr_src[row_start[d] + pos] = s;
}

// ---------------- layer 1: pre-GEMM aggregation ----------------

// A[i*32+c] = dinv[i] * x[i*18+c] (c<18), 0 otherwise. Padded for aligned 128B gathers.
__global__ void pad_x_kernel(const float* __restrict__ x) {
    int idx = blockIdx.x * blockDim.x + threadIdx.x;
    if (idx >= N_NODES * 32) return;
    int i = idx >> 5;
    int c = idx & 31;
    A_buf[idx] = (c < 18) ? dinv_buf[i] * x[i * 18 + c] : 0.0f;
}

// B[i] = dinv[i] * (A[i] + sum_{s in N(i)} A[s]); warp per node, 32-wide padded rows.
__global__ void agg_pre_kernel() {
    int w = (blockIdx.x * blockDim.x + threadIdx.x) >> 5;
    if (w >= N_NODES) return;
    int lane = threadIdx.x & 31;
    float a = A_buf[w * 32 + lane];  // self loop
    int beg = row_start[w], end = beg + deg_buf[w];
#pragma unroll 4
    for (int k = beg; k < end; k++) {
        a += A_buf[csr_src[k] * 32 + lane];
    }
    B_buf[w * 32 + lane] = dinv_buf[w] * a;
}

// h = relu(agg_x @ W + b): reads B (stride 32, 18 valid), writes A (stride 64).
__global__ void gemm1_relu_kernel(const float* __restrict__ W, const float* __restrict__ b) {
    __shared__ float Ws[18 * 64];
    __shared__ float bs[64];
    for (int t = threadIdx.x; t < 18 * 64; t += blockDim.x) Ws[t] = W[t];
    for (int t = threadIdx.x; t < 64; t += blockDim.x) bs[t] = b[t];
    __syncthreads();

    int i = blockIdx.x * blockDim.x + threadIdx.x;
    if (i >= N_NODES) return;

    float o[64];
#pragma unroll
    for (int j = 0; j < 64; j++) o[j] = bs[j];
#pragma unroll
    for (int k = 0; k < 18; k++) {
        float xv = B_buf[i * 32 + k];
#pragma unroll
        for (int j = 0; j < 64; j++) o[j] += xv * Ws[k * 64 + j];
    }
#pragma unroll
    for (int j = 0; j < 64; j++) A_buf[i * 64 + j] = fmaxf(o[j], 0.0f);
}

// ---------------- layers 2-4: GEMM then aggregate ----------------

// out[i] = dinv[i] * (in[i] @ W). IN_IS_A selects ping-pong direction.
template <int IN, int OUT, bool IN_IS_A>
__global__ void gemm_scale_kernel(const float* __restrict__ W) {
    __shared__ float Ws[IN * OUT];
    for (int t = threadIdx.x; t < IN * OUT; t += blockDim.x) Ws[t] = W[t];
    __syncthreads();

    int i = blockIdx.x * blockDim.x + threadIdx.x;
    if (i >= N_NODES) return;
    const float* xin = IN_IS_A ? A_buf : B_buf;
    float* gout = IN_IS_A ? B_buf : A_buf;

    float xr[IN];
    const float4* x4 = reinterpret_cast<const float4*>(&xin[i * IN]);
#pragma unroll
    for (int k4 = 0; k4 < IN / 4; k4++) {
        float4 v = x4[k4];
        xr[k4 * 4 + 0] = v.x; xr[k4 * 4 + 1] = v.y;
        xr[k4 * 4 + 2] = v.z; xr[k4 * 4 + 3] = v.w;
    }

    float o[OUT];
#pragma unroll
    for (int j = 0; j < OUT; j++) o[j] = 0.0f;
#pragma unroll
    for (int k = 0; k < IN; k++) {
#pragma unroll
        for (int j = 0; j < OUT; j++) o[j] += xr[k] * Ws[k * OUT + j];
    }
    float d = dinv_buf[i];
#pragma unroll
    for (int j = 0; j < OUT; j++) gout[i * OUT + j] = d * o[j];
}

// OUT=32: warp per node. out = relu(dinv*(self+sum) + b). B -> A
__global__ void agg32_kernel(const float* __restrict__ b) {
    int w = (blockIdx.x * blockDim.x + threadIdx.x) >> 5;
    if (w >= N_NODES) return;
    int lane = threadIdx.x & 31;
    float a = B_buf[w * 32 + lane];
    int beg = row_start[w], end = beg + deg_buf[w];
#pragma unroll 4
    for (int k = beg; k < end; k++) {
        a += B_buf[csr_src[k] * 32 + lane];
    }
    A_buf[w * 32 + lane] = fmaxf(fmaf(dinv_buf[w], a, b[lane]), 0.0f);
}

// OUT=16: 16 threads per node. B -> A
__global__ void agg16_kernel(const float* __restrict__ b) {
    int t = blockIdx.x * blockDim.x + threadIdx.x;
    int i = t >> 4;
    if (i >= N_NODES) return;
    int c = t & 15;
    float a = B_buf[i * 16 + c];
    int beg = row_start[i], end = beg + deg_buf[i];
#pragma unroll 4
    for (int k = beg; k < end; k++) {
        a += B_buf[csr_src[k] * 16 + c];
    }
    A_buf[i * 16 + c] = fmaxf(fmaf(dinv_buf[i], a, b[c]), 0.0f);
}

// OUT=2 final: thread per node, fused bias + log_softmax. B -> out
__global__ void agg2_logsoftmax_kernel(const float* __restrict__ b, float* __restrict__ out) {
    int i = blockIdx.x * blockDim.x + threadIdx.x;
    if (i >= N_NODES) return;
    const float2* g2 = reinterpret_cast<const float2*>(B_buf);
    float2 a = g2[i];
    int beg = row_start[i], end = beg + deg_buf[i];
#pragma unroll 4
    for (int k = beg; k < end; k++) {
        float2 v = g2[csr_src[k]];
        a.x += v.x; a.y += v.y;
    }
    float d = dinv_buf[i];
    float v0 = fmaf(d, a.x, b[0]);
    float v1 = fmaf(d, a.y, b[1]);
    float m = fmaxf(v0, v1);
    float lse = m + logf(expf(v0 - m) + expf(v1 - m));
    out[i * 2 + 0] = v0 - lse;
    out[i * 2 + 1] = v1 - lse;
}

// ---------------- launch ----------------

extern "C" void kernel_launch(void* const* d_in, const int* in_sizes, int n_in,
                              void* d_out, int out_size) {
    const float* x  = (const float*)d_in[0];
    const int*   ei = (const int*)d_in[1];
    const float* W1 = (const float*)d_in[2];
    const float* b1 = (const float*)d_in[3];
    const float* W2 = (const float*)d_in[4];
    const float* b2 = (const float*)d_in[5];
    const float* W3 = (const float*)d_in[6];
    const float* b3 = (const float*)d_in[7];
    const float* W4 = (const float*)d_in[8];
    const float* b4 = (const float*)d_in[9];
    float* out = (float*)d_out;

    const int T = 256;
    const int nodeB = (N_NODES + T - 1) / T;
    const int edgeB = (N_EDGES + T - 1) / T;
    const int warpNodeB = (N_NODES * 32 + T - 1) / T;

    // dtype detection + CSR build (group by dst)
    detect_dtype_kernel<<<1, 32>>>(ei);
    zero_counts_kernel<<<nodeB, T>>>();
    hist_kernel<<<edgeB, T>>>(ei);
    alloc_kernel<<<(N_NODES + 1023) / 1024, 1024>>>();
    fill_kernel<<<edgeB, T>>>(ei);

    // Layer 1: aggregate x (18-dim, padded 32) then GEMM 18->64 (+bias+relu)
    pad_x_kernel<<<(N_NODES * 32 + T - 1) / T, T>>>(x);
    agg_pre_kernel<<<warpNodeB, T>>>();
    gemm1_relu_kernel<<<nodeB, T>>>(W1, b1);

    // Layer 2: 64 -> 32  (A -> B), aggregate (B -> A)
    gemm_scale_kernel<64, 32, true><<<nodeB, T>>>(W2);
    agg32_kernel<<<warpNodeB, T>>>(b2);

    // Layer 3: 32 -> 16  (A -> B), aggregate (B -> A)
    gemm_scale_kernel<32, 16, true><<<nodeB, T>>>(W3);
    agg16_kernel<<<(N_NODES * 16 + T - 1) / T, T>>>(b3);

    // Layer 4: 16 -> 2  (A -> B), aggregate + log_softmax (B -> out)
    gemm_scale_kernel<16, 2, true><<<nodeB, T>>>(W4);
    agg2_logsoftmax_kernel<<<nodeB, T>>>(b4, out);
}

// round 5
// speedup vs baseline: 1.7063x; 1.2804x over previous
#include <cuda_runtime.h>

#define N_NODES 100000
#define N_EDGES 1600000

// Scratch (no cudaMalloc allowed). Ping-pong buffers A and B.
__device__ float A_buf[N_NODES * 32];
__device__ float B_buf[N_NODES * 32];
__device__ float dinv_buf[N_NODES];       // rsqrt(deg+1)
__device__ int   deg_buf[N_NODES];        // in-degree (excl self-loop)
__device__ int   row_start[N_NODES];      // CSR segment start (by dst, arbitrary order)
__device__ int   cursor_buf[N_NODES];     // fill cursors
__device__ int   csr_src[N_EDGES];        // src grouped by dst
__device__ int   is64_flag;               // 1 if edge_index is int64, 0 if int32
__device__ int   total_counter;           // segment allocator

__device__ __forceinline__ int load_src(const int* __restrict__ ei, int e, int is64) {
    return is64 ? ei[2 * e] : ei[e];
}
__device__ __forceinline__ int load_dst(const int* __restrict__ ei, int e, int is64) {
    return is64 ? ei[2 * (N_EDGES + e)] : ei[N_EDGES + e];
}

// ---------------- init: zero counts + dtype detect ----------------
// int64 little-endian with values < 2^31: every odd int32 word is 0.
__global__ void init_kernel(const int* __restrict__ ei) {
    int i = blockIdx.x * blockDim.x + threadIdx.x;
    if (i < N_NODES) { deg_buf[i] = 0; cursor_buf[i] = 0; }
    if (i == 0) {
        int any = 0;
        for (int k = 0; k < 64; k++) any |= ei[2 * k + 1];
        is64_flag = (any == 0) ? 1 : 0;
        total_counter = 0;
    }
}

__global__ void hist_kernel(const int* __restrict__ ei) {
    int e = blockIdx.x * blockDim.x + threadIdx.x;
    if (e >= N_EDGES) return;
    int d = load_dst(ei, e, is64_flag);
    atomicAdd(&deg_buf[d], 1);
}

__device__ __forceinline__ int block_inclusive_scan(int v, int tid) {
    __shared__ int warp_sums[32];
    int lane = tid & 31;
#pragma unroll
    for (int o = 1; o < 32; o <<= 1) {
        int n = __shfl_up_sync(0xffffffffu, v, o);
        if (lane >= o) v += n;
    }
    if (lane == 31) warp_sums[tid >> 5] = v;
    __syncthreads();
    if (tid < 32) {
        int w = warp_sums[tid];
#pragma unroll
        for (int o = 1; o < 32; o <<= 1) {
            int n = __shfl_up_sync(0xffffffffu, w, o);
            if (tid >= o) w += n;
        }
        warp_sums[tid] = w;
    }
    __syncthreads();
    return (tid >= 32) ? v + warp_sums[(tid >> 5) - 1] : v;
}

// Segment allocation (block scan + one atomic per block; cross-block order arbitrary)
// + fused pad: A[i*32+c] = dinv[i]*x[i*18+c] (c<18), else 0.
__global__ void alloc_pad_kernel(const float* __restrict__ x) {
    int tid = threadIdx.x;
    int i = blockIdx.x * 1024 + tid;
    int v = (i < N_NODES) ? deg_buf[i] : 0;
    int inc = block_inclusive_scan(v, tid);
    __shared__ int base_sh;
    if (tid == 1023) base_sh = atomicAdd(&total_counter, inc);
    __syncthreads();
    if (i < N_NODES) {
        row_start[i] = base_sh + inc - v;
        float d = rsqrtf((float)(v + 1));
        dinv_buf[i] = d;
        float r[32];
#pragma unroll
        for (int c = 0; c < 18; c++) r[c] = d * x[i * 18 + c];
#pragma unroll
        for (int c = 18; c < 32; c++) r[c] = 0.0f;
        float4* a4 = reinterpret_cast<float4*>(&A_buf[i * 32]);
#pragma unroll
        for (int q = 0; q < 8; q++)
            a4[q] = make_float4(r[q * 4], r[q * 4 + 1], r[q * 4 + 2], r[q * 4 + 3]);
    }
}

__global__ void fill_kernel(const int* __restrict__ ei) {
    int e = blockIdx.x * blockDim.x + threadIdx.x;
    if (e >= N_EDGES) return;
    int is64 = is64_flag;
    int s = load_src(ei, e, is64);
    int d = load_dst(ei, e, is64);
    int pos = atomicAdd(&cursor_buf[d], 1);
    csr_src[row_start[d] + pos] = s;
}

// ---------------- layer 1 aggregation (pre-GEMM, 32-wide padded) ----------------
// B[i] = dinv[i] * (A[i] + sum_{s in N(i)} A[s])
__global__ void agg_pre_kernel() {
    int w = (blockIdx.x * blockDim.x + threadIdx.x) >> 5;
    if (w >= N_NODES) return;
    int lane = threadIdx.x & 31;
    float a = A_buf[w * 32 + lane];  // self loop
    int beg = row_start[w], end = beg + deg_buf[w];
#pragma unroll 8
    for (int k = beg; k < end; k++) {
        a += A_buf[csr_src[k] * 32 + lane];
    }
    B_buf[w * 32 + lane] = dinv_buf[w] * a;
}

// ---------------- fused GEMM1(+relu)+GEMM2: B(aggx,32-pad) -> A(g32) ----------------
// h_k = relu(b1[k] + sum_m aggx_m W1[m,k]);  g_j = dinv * sum_k h_k W2[k,j]
__global__ void gemm12_kernel(const float* __restrict__ W1, const float* __restrict__ b1,
                              const float* __restrict__ W2) {
    __shared__ float W1s[18 * 64];
    __shared__ float W2s[64 * 32];
    __shared__ float b1s[64];
    for (int t = threadIdx.x; t < 18 * 64; t += blockDim.x) W1s[t] = W1[t];
    for (int t = threadIdx.x; t < 64 * 32; t += blockDim.x) W2s[t] = W2[t];
    for (int t = threadIdx.x; t < 64; t += blockDim.x) b1s[t] = b1[t];
    __syncthreads();

    int i = blockIdx.x * blockDim.x + threadIdx.x;
    if (i >= N_NODES) return;

    float xr[18];
    const float4* x4 = reinterpret_cast<const float4*>(&B_buf[i * 32]);
#pragma unroll
    for (int q = 0; q < 4; q++) {
        float4 v = x4[q];
        xr[q * 4 + 0] = v.x; xr[q * 4 + 1] = v.y; xr[q * 4 + 2] = v.z; xr[q * 4 + 3] = v.w;
    }
    { float2 v = reinterpret_cast<const float2*>(&B_buf[i * 32])[8]; xr[16] = v.x; xr[17] = v.y; }

    float o[32];
#pragma unroll
    for (int j = 0; j < 32; j++) o[j] = 0.0f;

#pragma unroll 4
    for (int k = 0; k < 64; k++) {
        float acc = b1s[k];
#pragma unroll
        for (int m = 0; m < 18; m++) acc += xr[m] * W1s[m * 64 + k];
        float h = fmaxf(acc, 0.0f);
#pragma unroll
        for (int j = 0; j < 32; j++) o[j] += h * W2s[k * 32 + j];
    }
    float d = dinv_buf[i];
    float4* a4 = reinterpret_cast<float4*>(&A_buf[i * 32]);
#pragma unroll
    for (int q = 0; q < 8; q++)
        a4[q] = make_float4(d * o[q * 4], d * o[q * 4 + 1], d * o[q * 4 + 2], d * o[q * 4 + 3]);
}

// ---------------- layer 2 agg + fused GEMM3: A(g32) -> B(g16) ----------------
// warp per node: h_lane = relu(dinv*(self+sum)+b2[lane]); lanes 0-15: g_j = dinv*sum_k h_k W3[k,j]
__global__ void agg32_g3_kernel(const float* __restrict__ b2, const float* __restrict__ W3) {
    __shared__ float W3s[32 * 16];
    for (int t = threadIdx.x; t < 32 * 16; t += blockDim.x) W3s[t] = W3[t];
    __syncthreads();

    int w = (blockIdx.x * blockDim.x + threadIdx.x) >> 5;
    if (w >= N_NODES) return;
    int lane = threadIdx.x & 31;
    float a = A_buf[w * 32 + lane];
    int beg = row_start[w], end = beg + deg_buf[w];
#pragma unroll 8
    for (int k = beg; k < end; k++) {
        a += A_buf[csr_src[k] * 32 + lane];
    }
    float d = dinv_buf[w];
    float h = fmaxf(fmaf(d, a, b2[lane]), 0.0f);

    // g16 via warp broadcast: all lanes shuffle, lanes 0-15 accumulate
    float o = 0.0f;
    int j = lane & 15;
#pragma unroll
    for (int k = 0; k < 32; k++) {
        float hk = __shfl_sync(0xffffffffu, h, k);
        o += hk * W3s[k * 16 + j];
    }
    if (lane < 16) B_buf[w * 16 + lane] = d * o;
}

// ---------------- layer 3 agg + fused GEMM4: B(g16) -> A(g2) ----------------
// 16 threads per node: h_c = relu(dinv*(self+sum)+b3[c]); butterfly-reduce h@W4 (16x2)
__global__ void agg16_g4_kernel(const float* __restrict__ b3, const float* __restrict__ W4) {
    int t = blockIdx.x * blockDim.x + threadIdx.x;
    int i = t >> 4;
    if (i >= N_NODES) return;
    int c = t & 15;
    float a = B_buf[i * 16 + c];
    int beg = row_start[i], end = beg + deg_buf[i];
#pragma unroll 8
    for (int k = beg; k < end; k++) {
        a += B_buf[csr_src[k] * 16 + c];
    }
    float d = dinv_buf[i];
    float h = fmaxf(fmaf(d, a, b3[c]), 0.0f);

    float v0 = h * W4[c * 2 + 0];
    float v1 = h * W4[c * 2 + 1];
#pragma unroll
    for (int o = 8; o >= 1; o >>= 1) {
        v0 += __shfl_xor_sync(0xffffffffu, v0, o);
        v1 += __shfl_xor_sync(0xffffffffu, v1, o);
    }
    if (c == 0) {
        A_buf[i * 2 + 0] = d * v0;
        A_buf[i * 2 + 1] = d * v1;
    }
}

// ---------------- final: agg + bias + log_softmax: A(g2) -> out ----------------
__global__ void agg2_logsoftmax_kernel(const float* __restrict__ b, float* __restrict__ out) {
    int i = blockIdx.x * blockDim.x + threadIdx.x;
    if (i >= N_NODES) return;
    const float2* g2 = reinterpret_cast<const float2*>(A_buf);
    float2 a = g2[i];
    int beg = row_start[i], end = beg + deg_buf[i];
#pragma unroll 8
    for (int k = beg; k < end; k++) {
        float2 v = g2[csr_src[k]];
        a.x += v.x; a.y += v.y;
    }
    float d = dinv_buf[i];
    float v0 = fmaf(d, a.x, b[0]);
    float v1 = fmaf(d, a.y, b[1]);
    float m = fmaxf(v0, v1);
    float lse = m + logf(expf(v0 - m) + expf(v1 - m));
    out[i * 2 + 0] = v0 - lse;
    out[i * 2 + 1] = v1 - lse;
}

// ---------------- launch ----------------

extern "C" void kernel_launch(void* const* d_in, const int* in_sizes, int n_in,
                              void* d_out, int out_size) {
    const float* x  = (const float*)d_in[0];
    const int*   ei = (const int*)d_in[1];
    const float* W1 = (const float*)d_in[2];
    const float* b1 = (const float*)d_in[3];
    const float* W2 = (const float*)d_in[4];
    const float* b2 = (const float*)d_in[5];
    const float* W3 = (const float*)d_in[6];
    const float* b3 = (const float*)d_in[7];
    const float* W4 = (const float*)d_in[8];
    const float* b4 = (const float*)d_in[9];
    float* out = (float*)d_out;

    const int T = 256;
    const int nodeB = (N_NODES + T - 1) / T;
    const int edgeB = (N_EDGES + T - 1) / T;
    const int warpNodeB = (N_NODES * 32 + T - 1) / T;

    // CSR build (group by dst)
    init_kernel<<<nodeB, T>>>(ei);
    hist_kernel<<<edgeB, T>>>(ei);
    alloc_pad_kernel<<<(N_NODES + 1023) / 1024, 1024>>>(x);
    fill_kernel<<<edgeB, T>>>(ei);

    // Layer 1 agg (pre-GEMM), then fused GEMM1+relu+GEMM2
    agg_pre_kernel<<<warpNodeB, T>>>();
    gemm12_kernel<<<nodeB, T>>>(W1, b1, W2);

    // Layer 2 agg + fused GEMM3
    agg32_g3_kernel<<<warpNodeB, T>>>(b2, W3);

    // Layer 3 agg + fused GEMM4
    agg16_g4_kernel<<<(N_NODES * 16 + T - 1) / T, T>>>(b3, W4);

    // Layer 4 agg + log_softmax
    agg2_logsoftmax_kernel<<<nodeB, T>>>(b4, out);
}

// round 6
// speedup vs baseline: 1.7095x; 1.0019x over previous
#include <cuda_runtime.h>

#define N_NODES 100000
#define N_EDGES 1600000

// Scratch (no cudaMalloc allowed). Ping-pong buffers A and B.
__device__ float A_buf[N_NODES * 32];
__device__ float B_buf[N_NODES * 32];
__device__ float dinv_buf[N_NODES];       // rsqrt(deg+1)
__device__ int   deg_buf[N_NODES];        // in-degree (excl self-loop)
__device__ int   row_start[N_NODES];      // CSR segment start (by dst, arbitrary order)
__device__ int   cursor_buf[N_NODES];     // fill cursors (init = row_start)
__device__ int   csr_src[N_EDGES];        // src grouped by dst
__device__ int   is64_flag;               // 1 if edge_index is int64, 0 if int32
__device__ int   total_counter;           // segment allocator

// ---------------- init: zero counts + dtype detect ----------------
// int64 little-endian with values < 2^31: every odd int32 word is 0.
__global__ void init_kernel(const int* __restrict__ ei) {
    int i = blockIdx.x * blockDim.x + threadIdx.x;
    if (i < N_NODES) deg_buf[i] = 0;
    if (i == 0) {
        int any = 0;
        for (int k = 0; k < 64; k++) any |= ei[2 * k + 1];
        is64_flag = (any == 0) ? 1 : 0;
        total_counter = 0;
    }
}

// 2 edges per thread, vectorized loads
__global__ void hist_kernel(const int* __restrict__ ei) {
    int t = blockIdx.x * blockDim.x + threadIdx.x;
    if (t >= N_EDGES / 2) return;
    if (is64_flag) {
        const int4* pd = reinterpret_cast<const int4*>(ei);
        int4 d = pd[N_EDGES / 2 + t];  // dst int64 pair: low words at .x, .z
        atomicAdd(&deg_buf[d.x], 1);
        atomicAdd(&deg_buf[d.z], 1);
    } else {
        const int2* pd = reinterpret_cast<const int2*>(ei + N_EDGES);
        int2 d = pd[t];
        atomicAdd(&deg_buf[d.x], 1);
        atomicAdd(&deg_buf[d.y], 1);
    }
}

__device__ __forceinline__ int block_inclusive_scan(int v, int tid) {
    __shared__ int warp_sums[32];
    int lane = tid & 31;
#pragma unroll
    for (int o = 1; o < 32; o <<= 1) {
        int n = __shfl_up_sync(0xffffffffu, v, o);
        if (lane >= o) v += n;
    }
    if (lane == 31) warp_sums[tid >> 5] = v;
    __syncthreads();
    if (tid < 32) {
        int w = warp_sums[tid];
#pragma unroll
        for (int o = 1; o < 32; o <<= 1) {
            int n = __shfl_up_sync(0xffffffffu, w, o);
            if (tid >= o) w += n;
        }
        warp_sums[tid] = w;
    }
    __syncthreads();
    return (tid >= 32) ? v + warp_sums[(tid >> 5) - 1] : v;
}

// Segment allocation (block scan + one atomic per block; cross-block order arbitrary)
// + cursor init + fused pad: A[i*32+c] = dinv[i]*x[i*18+c] (c<18), else 0.
__global__ void alloc_pad_kernel(const float* __restrict__ x) {
    int tid = threadIdx.x;
    int i = blockIdx.x * 1024 + tid;
    int v = (i < N_NODES) ? deg_buf[i] : 0;
    int inc = block_inclusive_scan(v, tid);
    __shared__ int base_sh;
    if (tid == 1023) base_sh = atomicAdd(&total_counter, inc);
    __syncthreads();
    if (i < N_NODES) {
        int rs = base_sh + inc - v;
        row_start[i] = rs;
        cursor_buf[i] = rs;
        float d = rsqrtf((float)(v + 1));
        dinv_buf[i] = d;
        float r[32];
#pragma unroll
        for (int c = 0; c < 18; c++) r[c] = d * x[i * 18 + c];
#pragma unroll
        for (int c = 18; c < 32; c++) r[c] = 0.0f;
        float4* a4 = reinterpret_cast<float4*>(&A_buf[i * 32]);
#pragma unroll
        for (int q = 0; q < 8; q++)
            a4[q] = make_float4(r[q * 4], r[q * 4 + 1], r[q * 4 + 2], r[q * 4 + 3]);
    }
}

// 2 edges per thread; cursor pre-initialized to row_start
__global__ void fill_kernel(const int* __restrict__ ei) {
    int t = blockIdx.x * blockDim.x + threadIdx.x;
    if (t >= N_EDGES / 2) return;
    int s0, s1, d0, d1;
    if (is64_flag) {
        const int4* p = reinterpret_cast<const int4*>(ei);
        int4 s = p[t];
        int4 d = p[N_EDGES / 2 + t];
        s0 = s.x; s1 = s.z; d0 = d.x; d1 = d.z;
    } else {
        const int2* ps = reinterpret_cast<const int2*>(ei);
        const int2* pd = reinterpret_cast<const int2*>(ei + N_EDGES);
        int2 s = ps[t];
        int2 d = pd[t];
        s0 = s.x; s1 = s.y; d0 = d.x; d1 = d.y;
    }
    int p0 = atomicAdd(&cursor_buf[d0], 1);
    int p1 = atomicAdd(&cursor_buf[d1], 1);
    csr_src[p0] = s0;
    csr_src[p1] = s1;
}

// ---------------- layer 1 aggregation (pre-GEMM, 32-wide padded) ----------------
// B[i] = dinv[i] * (A[i] + sum_{s in N(i)} A[s])
__global__ void agg_pre_kernel() {
    int w = (blockIdx.x * blockDim.x + threadIdx.x) >> 5;
    if (w >= N_NODES) return;
    int lane = threadIdx.x & 31;
    float a = A_buf[w * 32 + lane];  // self loop
    int beg = row_start[w], end = beg + deg_buf[w];
#pragma unroll 8
    for (int k = beg; k < end; k++) {
        a += A_buf[csr_src[k] * 32 + lane];
    }
    B_buf[w * 32 + lane] = dinv_buf[w] * a;
}

// ---------------- fused GEMM1(+relu)+GEMM2: B(aggx,32-pad) -> A(g32) ----------------
// h_k = relu(b1[k] + sum_m aggx_m W1[m,k]);  g_j = dinv * sum_k h_k W2[k,j]
// W1 transposed in smem with padded stride 20 (16B-aligned rows) for LDS.128.
__global__ void gemm12_kernel(const float* __restrict__ W1, const float* __restrict__ b1,
                              const float* __restrict__ W2) {
    __shared__ float W1t[64 * 20];
    __shared__ float W2s[64 * 32];
    __shared__ float b1s[64];
    for (int t = threadIdx.x; t < 18 * 64; t += blockDim.x) {
        int m = t / 64, k = t % 64;
        W1t[k * 20 + m] = W1[t];
    }
    for (int t = threadIdx.x; t < 64 * 32; t += blockDim.x) W2s[t] = W2[t];
    for (int t = threadIdx.x; t < 64; t += blockDim.x) b1s[t] = b1[t];
    __syncthreads();

    int i = blockIdx.x * blockDim.x + threadIdx.x;
    if (i >= N_NODES) return;

    float xr[18];
    const float4* x4 = reinterpret_cast<const float4*>(&B_buf[i * 32]);
#pragma unroll
    for (int q = 0; q < 4; q++) {
        float4 v = x4[q];
        xr[q * 4 + 0] = v.x; xr[q * 4 + 1] = v.y; xr[q * 4 + 2] = v.z; xr[q * 4 + 3] = v.w;
    }
    { float2 v = reinterpret_cast<const float2*>(&B_buf[i * 32])[8]; xr[16] = v.x; xr[17] = v.y; }

    float o[32];
#pragma unroll
    for (int j = 0; j < 32; j++) o[j] = 0.0f;

#pragma unroll 2
    for (int k = 0; k < 64; k++) {
        const float4* w1 = reinterpret_cast<const float4*>(&W1t[k * 20]);
        float acc = b1s[k];
#pragma unroll
        for (int q = 0; q < 4; q++) {
            float4 w = w1[q];
            acc += xr[q * 4 + 0] * w.x + xr[q * 4 + 1] * w.y
                 + xr[q * 4 + 2] * w.z + xr[q * 4 + 3] * w.w;
        }
        acc += xr[16] * W1t[k * 20 + 16] + xr[17] * W1t[k * 20 + 17];
        float h = fmaxf(acc, 0.0f);
        const float4* w2 = reinterpret_cast<const float4*>(&W2s[k * 32]);
#pragma unroll
        for (int q = 0; q < 8; q++) {
            float4 w = w2[q];
            o[q * 4 + 0] += h * w.x; o[q * 4 + 1] += h * w.y;
            o[q * 4 + 2] += h * w.z; o[q * 4 + 3] += h * w.w;
        }
    }
    float d = dinv_buf[i];
    float4* a4 = reinterpret_cast<float4*>(&A_buf[i * 32]);
#pragma unroll
    for (int q = 0; q < 8; q++)
        a4[q] = make_float4(d * o[q * 4], d * o[q * 4 + 1], d * o[q * 4 + 2], d * o[q * 4 + 3]);
}

// ---------------- layer 2 agg + fused GEMM3: A(g32) -> B(g16) ----------------
__global__ void agg32_g3_kernel(const float* __restrict__ b2, const float* __restrict__ W3) {
    __shared__ float W3s[32 * 16];
    for (int t = threadIdx.x; t < 32 * 16; t += blockDim.x) W3s[t] = W3[t];
    __syncthreads();

    int w = (blockIdx.x * blockDim.x + threadIdx.x) >> 5;
    if (w >= N_NODES) return;
    int lane = threadIdx.x & 31;
    float a = A_buf[w * 32 + lane];
    int beg = row_start[w], end = beg + deg_buf[w];
#pragma unroll 8
    for (int k = beg; k < end; k++) {
        a += A_buf[csr_src[k] * 32 + lane];
    }
    float d = dinv_buf[w];
    float h = fmaxf(fmaf(d, a, b2[lane]), 0.0f);

    // g16 via warp broadcast: all lanes shuffle, lanes 0-15 accumulate
    float o = 0.0f;
    int j = lane & 15;
#pragma unroll
    for (int k = 0; k < 32; k++) {
        float hk = __shfl_sync(0xffffffffu, h, k);
        o += hk * W3s[k * 16 + j];
    }
    if (lane < 16) B_buf[w * 16 + lane] = d * o;
}

// ---------------- layer 3 agg + fused GEMM4: B(g16) -> A(g2) ----------------
__global__ void agg16_g4_kernel(const float* __restrict__ b3, const float* __restrict__ W4) {
    int t = blockIdx.x * blockDim.x + threadIdx.x;
    int i = t >> 4;
    if (i >= N_NODES) return;
    int c = t & 15;
    float a = B_buf[i * 16 + c];
    int beg = row_start[i], end = beg + deg_buf[i];
#pragma unroll 8
    for (int k = beg; k < end; k++) {
        a += B_buf[csr_src[k] * 16 + c];
    }
    float d = dinv_buf[i];
    float h = fmaxf(fmaf(d, a, b3[c]), 0.0f);

    float v0 = h * W4[c * 2 + 0];
    float v1 = h * W4[c * 2 + 1];
#pragma unroll
    for (int o = 8; o >= 1; o >>= 1) {
        v0 += __shfl_xor_sync(0xffffffffu, v0, o);
        v1 += __shfl_xor_sync(0xffffffffu, v1, o);
    }
    if (c == 0) {
        A_buf[i * 2 + 0] = d * v0;
        A_buf[i * 2 + 1] = d * v1;
    }
}

// ---------------- final: agg + bias + log_softmax: A(g2) -> out ----------------
__global__ void agg2_logsoftmax_kernel(const float* __restrict__ b, float* __restrict__ out) {
    int i = blockIdx.x * blockDim.x + threadIdx.x;
    if (i >= N_NODES) return;
    const float2* g2 = reinterpret_cast<const float2*>(A_buf);
    float2 a = g2[i];
    int beg = row_start[i], end = beg + deg_buf[i];
#pragma unroll 8
    for (int k = beg; k < end; k++) {
        float2 v = g2[csr_src[k]];
        a.x += v.x; a.y += v.y;
    }
    float d = dinv_buf[i];
    float v0 = fmaf(d, a.x, b[0]);
    float v1 = fmaf(d, a.y, b[1]);
    float m = fmaxf(v0, v1);
    float lse = m + logf(expf(v0 - m) + expf(v1 - m));
    out[i * 2 + 0] = v0 - lse;
    out[i * 2 + 1] = v1 - lse;
}

// ---------------- launch ----------------

extern "C" void kernel_launch(void* const* d_in, const int* in_sizes, int n_in,
                              void* d_out, int out_size) {
    const float* x  = (const float*)d_in[0];
    const int*   ei = (const int*)d_in[1];
    const float* W1 = (const float*)d_in[2];
    const float* b1 = (const float*)d_in[3];
    const float* W2 = (const float*)d_in[4];
    const float* b2 = (const float*)d_in[5];
    const float* W3 = (const float*)d_in[6];
    const float* b3 = (const float*)d_in[7];
    const float* W4 = (const float*)d_in[8];
    const float* b4 = (const float*)d_in[9];
    float* out = (float*)d_out;

    const int T = 256;
    const int nodeB = (N_NODES + T - 1) / T;
    const int halfEdgeB = (N_EDGES / 2 + T - 1) / T;
    const int warpNodeB = (N_NODES * 32 + T - 1) / T;

    // CSR build (group by dst)
    init_kernel<<<nodeB, T>>>(ei);
    hist_kernel<<<halfEdgeB, T>>>(ei);
    alloc_pad_kernel<<<(N_NODES + 1023) / 1024, 1024>>>(x);
    fill_kernel<<<halfEdgeB, T>>>(ei);

    // Layer 1 agg (pre-GEMM), then fused GEMM1+relu+GEMM2
    agg_pre_kernel<<<warpNodeB, T>>>();
    gemm12_kernel<<<nodeB, T>>>(W1, b1, W2);

    // Layer 2 agg + fused GEMM3
    agg32_g3_kernel<<<warpNodeB, T>>>(b2, W3);

    // Layer 3 agg + fused GEMM4
    agg16_g4_kernel<<<(N_NODES * 16 + T - 1) / T, T>>>(b3, W4);

    // Layer 4 agg + log_softmax
    agg2_logsoftmax_kernel<<<nodeB, T>>>(b4, out);
}